// round 1
// baseline (speedup 1.0000x reference)
#include <cuda_runtime.h>

// img: [256, 3, 224, 224] f32, y_idx/x_idx: [256] i32.
// out[b,c,h,w] = img * (0 if h in [y,y+32) && w in [x,x+32) else 1)
//
// Pure HBM-streaming kernel: float4 vectorized, fully coalesced.
// W=224 -> 56 float4 per row; each (b,c) plane contiguous.

#define SQ 32
#define BATCH 256
#define CH 3
#define HH 224
#define WW 224
#define W4 (WW / 4)           // 56
#define ROWS_PER_BLK 8

__global__ __launch_bounds__(W4 * ROWS_PER_BLK)
void random_square_dropout_kernel(const float4* __restrict__ img,
                                  const int* __restrict__ y_idx,
                                  const int* __restrict__ x_idx,
                                  float4* __restrict__ out) {
    const int b  = blockIdx.z;
    const int c  = blockIdx.y;
    const int h  = blockIdx.x * ROWS_PER_BLK + threadIdx.y;
    const int w4 = threadIdx.x;                 // 0..55

    const int y = __ldg(&y_idx[b]);
    const int x = __ldg(&x_idx[b]);

    const long plane = ((long)b * CH + c) * (long)(HH * W4);
    const long idx   = plane + (long)h * W4 + w4;

    float4 v = img[idx];

    if (h >= y && h < y + SQ) {
        const int w0 = w4 * 4;
        // float4 overlaps [x, x+SQ) ?
        if (w0 + 3 >= x && w0 < x + SQ) {
            if (w0     >= x && w0     < x + SQ) v.x = 0.0f;
            if (w0 + 1 >= x && w0 + 1 < x + SQ) v.y = 0.0f;
            if (w0 + 2 >= x && w0 + 2 < x + SQ) v.z = 0.0f;
            if (w0 + 3 >= x && w0 + 3 < x + SQ) v.w = 0.0f;
        }
    }

    out[idx] = v;
}

extern "C" void kernel_launch(void* const* d_in, const int* in_sizes, int n_in,
                              void* d_out, int out_size) {
    const float4* img = (const float4*)d_in[0];
    const int* y_idx  = (const int*)d_in[1];
    const int* x_idx  = (const int*)d_in[2];
    float4* out       = (float4*)d_out;

    dim3 block(W4, ROWS_PER_BLK);                 // 56 x 8 = 448 threads
    dim3 grid(HH / ROWS_PER_BLK, CH, BATCH);      // 28 x 3 x 256
    random_square_dropout_kernel<<<grid, block>>>(img, y_idx, x_idx, out);
}

// round 2
// speedup vs baseline: 1.0776x; 1.0776x over previous
#include <cuda_runtime.h>

// img: [256, 3, 224, 224] f32, y_idx/x_idx: [256] i32.
// out[b,c,h,w] = img * (0 if h in [y,y+32) && w in [x,x+32) else 1)
//
// HBM-streaming kernel, MLP=4: each thread loads 4 coalesced float4s
// (rows h0, h0+8, h0+16, h0+24 of a 32-row tile) up front, masks, stores.
// __ldcs/__stcs streaming hints — data has zero reuse.

#define SQ 32
#define BATCH 256
#define CH 3
#define HH 224
#define WW 224
#define W4 (WW / 4)           // 56 float4 per row
#define TY 8                  // threads in y
#define ROWS_PER_THREAD 4
#define TILE_H (TY * ROWS_PER_THREAD)   // 32 rows per block

__global__ __launch_bounds__(W4 * TY)
void random_square_dropout_kernel(const float4* __restrict__ img,
                                  const int* __restrict__ y_idx,
                                  const int* __restrict__ x_idx,
                                  float4* __restrict__ out) {
    const int b  = blockIdx.z;
    const int c  = blockIdx.y;
    const int h0 = blockIdx.x * TILE_H + threadIdx.y;  // rows h0 + 8*k
    const int w4 = threadIdx.x;                        // 0..55

    const int y = __ldg(&y_idx[b]);
    const int x = __ldg(&x_idx[b]);

    const long plane = ((long)b * CH + c) * (long)(HH * W4);
    const long base  = plane + (long)h0 * W4 + w4;

    // Front-batched loads: 4 independent DRAM requests in flight.
    float4 v0 = __ldcs(&img[base]);
    float4 v1 = __ldcs(&img[base +  TY * W4]);
    float4 v2 = __ldcs(&img[base + 2 * TY * W4]);
    float4 v3 = __ldcs(&img[base + 3 * TY * W4]);

    // Column in-square flags (constant across the 4 rows of this thread).
    const int w0 = w4 * 4;
    const bool cx0 = (w0     >= x) && (w0     < x + SQ);
    const bool cx1 = (w0 + 1 >= x) && (w0 + 1 < x + SQ);
    const bool cx2 = (w0 + 2 >= x) && (w0 + 2 < x + SQ);
    const bool cx3 = (w0 + 3 >= x) && (w0 + 3 < x + SQ);
    const bool any_col = cx0 || cx1 || cx2 || cx3;

    if (any_col) {
        const bool r0 = (h0            >= y) && (h0            < y + SQ);
        const bool r1 = (h0 +     TY   >= y) && (h0 +     TY   < y + SQ);
        const bool r2 = (h0 + 2 * TY   >= y) && (h0 + 2 * TY   < y + SQ);
        const bool r3 = (h0 + 3 * TY   >= y) && (h0 + 3 * TY   < y + SQ);

        if (r0) { if (cx0) v0.x = 0.f; if (cx1) v0.y = 0.f; if (cx2) v0.z = 0.f; if (cx3) v0.w = 0.f; }
        if (r1) { if (cx0) v1.x = 0.f; if (cx1) v1.y = 0.f; if (cx2) v1.z = 0.f; if (cx3) v1.w = 0.f; }
        if (r2) { if (cx0) v2.x = 0.f; if (cx1) v2.y = 0.f; if (cx2) v2.z = 0.f; if (cx3) v2.w = 0.f; }
        if (r3) { if (cx0) v3.x = 0.f; if (cx1) v3.y = 0.f; if (cx2) v3.z = 0.f; if (cx3) v3.w = 0.f; }
    }

    __stcs(&out[base],              v0);
    __stcs(&out[base +  TY * W4],   v1);
    __stcs(&out[base + 2 * TY * W4], v2);
    __stcs(&out[base + 3 * TY * W4], v3);
}

extern "C" void kernel_launch(void* const* d_in, const int* in_sizes, int n_in,
                              void* d_out, int out_size) {
    const float4* img = (const float4*)d_in[0];
    const int* y_idx  = (const int*)d_in[1];
    const int* x_idx  = (const int*)d_in[2];
    float4* out       = (float4*)d_out;

    dim3 block(W4, TY);                      // 56 x 8 = 448 threads
    dim3 grid(HH / TILE_H, CH, BATCH);       // 7 x 3 x 256 = 5376 blocks
    random_square_dropout_kernel<<<grid, block>>>(img, y_idx, x_idx, out);
}